// round 15
// baseline (speedup 1.0000x reference)
#include <cuda_runtime.h>

#define NQ     1224
#define TWOQ   2448
#define SMAX   50
#define SM1    (SMAX - 1)
#define ROWS   (1024 * SM1)            // 50176
#define VEC4   (TWOQ / 4)              // 612 float4 per batch row
#define WPB    8
#define THREADS 256
#define RPW    3                       // rows per warp (3 concurrent streams)
#define NWARPS ((ROWS + RPW - 1) / RPW)          // 16726
#define BLOCKS ((NWARPS + WPB - 1) / WPB)        // 2091
#define FULLM  0xffffffffu
#define NBUCK  64
#define BSTRIDE 32                     // pad buckets to separate 128B lines
#define CMAIN  576                     // main loop covers float4 [0,576): i1 max 575

__device__ float    g_partials[NBUCK * BSTRIDE];   // zero-init at load
__device__ unsigned g_count;                        // zero-init at load

__device__ __forceinline__ unsigned nz4(const float4& v) {
    return __float_as_uint(v.x) | __float_as_uint(v.y) |
           __float_as_uint(v.z) | __float_as_uint(v.w);
}

__device__ __forceinline__ int locate4(const float4& v, int i) {
    int base = i * 4;
    if (v.x != 0.0f) return base;
    if (v.y != 0.0f) return base + 1;
    if (v.z != 0.0f) return base + 2;
    return base + 3;
}

// off(row) = (b*SMAX + t) * VEC4 with b = row/SM1, t = row%SM1 + 1
//          = (row + row/SM1 + 1) * VEC4     (32-bit safe: < 31.3M)
__device__ __forceinline__ int row_off4(int row) {
    return (row + row / SM1 + 1) * VEC4;
}
// pred row offset for (b, t-1): (b*SMAX + t - 1) * NQ = (row + row/SM1) * NQ
__device__ __forceinline__ int pred_off(int row) {
    return (row + row / SM1) * NQ;
}

// Rare path: the one-hot is in this stream's current 256-float window.
// Re-load the two chunks (L1-hit: they were just read) and locate exactly.
// Keeping the float4s out of the common path caps register pressure.
__device__ __forceinline__ int resolve(const float4* __restrict__ batch4,
                                       int off, int i0, int i1, bool i1ok,
                                       unsigned hit) {
    int loc = -1;
    if (hit) {
        float4 v0 = batch4[off + i0];
        if (nz4(v0)) loc = locate4(v0, i0);
        else if (i1ok) {
            float4 v1 = batch4[off + i1];
            loc = locate4(v1, i1);
        }
    }
    return __reduce_max_sync(FULLM, loc);
}

__global__ __launch_bounds__(THREADS, 8)
void loss_kernel(const float* __restrict__ pred,
                 const float* __restrict__ batch,
                 float* __restrict__ out) {
    __shared__ float warp_part[WPB];

    const int wid  = threadIdx.x >> 5;
    const int lane = threadIdx.x & 31;
    const int gw   = blockIdx.x * WPB + wid;       // 0..16727

    const int row0 = gw * RPW;                      // 3 consecutive rows
    // invalid rows (tail) start pre-resolved with no contribution
    int j0 = (row0     < ROWS) ? -1 : -2;
    int j1 = (row0 + 1 < ROWS) ? -1 : -2;
    int j2 = (row0 + 2 < ROWS) ? -1 : -2;

    const int off0 = row_off4(row0);
    const int off1 = row_off4(row0 + 1);
    const int off2 = row_off4(row0 + 2);

    const float4* __restrict__ batch4 = (const float4*)batch;

    // Three concurrent streams, 2 LDG.128/lane/stream (C = 256 floats):
    // 3 KB/warp in flight at start, detection granularity 256.
    // Only the OR-words survive the common path; exact locate re-loads
    // from L1 inside the rare hit branch (keeps regs <= ~32).
    #pragma unroll 1
    for (int c = 0; c < CMAIN; c += 64) {
        const int i0 = c + lane;            // max 543+... (c<=512: i0<=543)
        const int i1 = i0 + 32;             // max 575 < 612 (all in-bounds)
        unsigned n0 = 0, n1 = 0, n2 = 0;
        if (j0 == -1) n0 = nz4(batch4[off0 + i0]) | nz4(batch4[off0 + i1]);
        if (j1 == -1) n1 = nz4(batch4[off1 + i0]) | nz4(batch4[off1 + i1]);
        if (j2 == -1) n2 = nz4(batch4[off2 + i0]) | nz4(batch4[off2 + i1]);

        if (__ballot_sync(FULLM, n0 | n1 | n2)) {
            int t;
            t = resolve(batch4, off0, i0, i1, true, n0);
            if (j0 == -1 && t >= 0) j0 = t;
            t = resolve(batch4, off1, i0, i1, true, n1);
            if (j1 == -1 && t >= 0) j1 = t;
            t = resolve(batch4, off2, i0, i1, true, n2);
            if (j2 == -1 && t >= 0) j2 = t;
            if ((j0 != -1) & (j1 != -1) & (j2 != -1)) break;
        }
    }

    // Tail window: float4 [576, 612). i0 = 576+lane all valid (<= 607);
    // i1 = 608+lane valid only for lanes 0..3.
    if ((j0 == -1) | (j1 == -1) | (j2 == -1)) {
        const int i0 = CMAIN + lane;
        const int i1 = i0 + 32;
        const bool g = (i1 < VEC4);
        unsigned n0 = 0, n1 = 0, n2 = 0;
        if (j0 == -1) {
            n0 = nz4(batch4[off0 + i0]);
            if (g) n0 |= nz4(batch4[off0 + i1]);
        }
        if (j1 == -1) {
            n1 = nz4(batch4[off1 + i0]);
            if (g) n1 |= nz4(batch4[off1 + i1]);
        }
        if (j2 == -1) {
            n2 = nz4(batch4[off2 + i0]);
            if (g) n2 |= nz4(batch4[off2 + i1]);
        }
        int t;
        t = resolve(batch4, off0, i0, i1, g, n0);
        if (j0 == -1 && t >= 0) j0 = t;
        t = resolve(batch4, off1, i0, i1, g, n1);
        if (j1 == -1 && t >= 0) j1 = t;
        t = resolve(batch4, off2, i0, i1, g, n2);
        if (j2 == -1 && t >= 0) j2 = t;
    }

    // Per-warp epilogue (lane 0): issue all pred gathers back-to-back,
    // then the logs.  j >= 0 iff this row found its one-hot.
    if (lane == 0) {
        float contrib = 0.0f;
        float p0 = 0.f, p1 = 0.f, p2 = 0.f;
        if (j0 >= 0)
            p0 = __ldg(pred + pred_off(row0)     + ((j0 < NQ) ? j0 : j0 - NQ));
        if (j1 >= 0)
            p1 = __ldg(pred + pred_off(row0 + 1) + ((j1 < NQ) ? j1 : j1 - NQ));
        if (j2 >= 0)
            p2 = __ldg(pred + pred_off(row0 + 2) + ((j2 < NQ) ? j2 : j2 - NQ));
        if (j0 >= 0 && p0 > 0.0f) contrib -= __logf((j0 < NQ) ? p0 : 1.0f - p0);
        if (j1 >= 0 && p1 > 0.0f) contrib -= __logf((j1 < NQ) ? p1 : 1.0f - p1);
        if (j2 >= 0 && p2 > 0.0f) contrib -= __logf((j2 < NQ) ? p2 : 1.0f - p2);
        warp_part[wid] = contrib;
    }
    __syncthreads();

    // CTA epilogue: bucketed atomic (2091 CTAs over 64 padded lines =
    // ~33 ops/address, invisible), last CTA folds the final reduction.
    if (threadIdx.x == 0) {
        float s = 0.0f;
        #pragma unroll
        for (int w = 0; w < WPB; ++w) s += warp_part[w];
        atomicAdd(&g_partials[(blockIdx.x & (NBUCK - 1)) * BSTRIDE], s);
        __threadfence();
        const unsigned prev = atomicAdd(&g_count, 1u);
        if (prev == BLOCKS - 1) {
            float tot = 0.0f;
            #pragma unroll
            for (int i = 0; i < NBUCK; ++i)
                tot += atomicExch(&g_partials[i * BSTRIDE], 0.0f); // read+reset
            out[0] = tot;
            atomicExch(&g_count, 0u);   // reset for next graph replay
        }
    }
}

extern "C" void kernel_launch(void* const* d_in, const int* in_sizes, int n_in,
                              void* d_out, int out_size) {
    const float* pred  = (const float*)d_in[0];
    const float* batch = (const float*)d_in[1];
    float* out = (float*)d_out;

    loss_kernel<<<BLOCKS, THREADS>>>(pred, batch, out);
}

// round 16
// speedup vs baseline: 1.0788x; 1.0788x over previous
#include <cuda_runtime.h>

#define NQ     1224
#define TWOQ   2448
#define SMAX   50
#define SM1    (SMAX - 1)
#define ROWS   (1024 * SM1)            // 50176
#define VEC4   (TWOQ / 4)              // 612 float4 per batch row
#define ROW4   VEC4
#define WPB    8
#define THREADS 256
#define BLOCKS (ROWS / (WPB * 2))      // 3136 (2 rows per warp)
#define FULLM  0xffffffffu
#define NBUCK  64
#define BSTRIDE 32                     // pad buckets to separate 128B lines

__device__ float    g_partials[NBUCK * BSTRIDE];   // zero-init at load
__device__ unsigned g_count;                        // zero-init at load

__device__ __forceinline__ unsigned nz4(const float4& v) {
    return __float_as_uint(v.x) | __float_as_uint(v.y) |
           __float_as_uint(v.z) | __float_as_uint(v.w);
}

__device__ __forceinline__ int locate4(const float4& v, int i) {
    int base = i * 4;
    if (v.x != 0.0f) return base;
    if (v.y != 0.0f) return base + 1;
    if (v.z != 0.0f) return base + 2;
    return base + 3;
}

// position within the (v0 @ i0, v1 @ i1) pair; caller guarantees nonzero
__device__ __forceinline__ int locate_pair(const float4& v0, const float4& v1,
                                           int i0, int i1) {
    return nz4(v0) ? locate4(v0, i0) : locate4(v1, i1);
}

__global__ __launch_bounds__(THREADS, 8)
void loss_kernel(const float* __restrict__ pred,
                 const float* __restrict__ batch,
                 float* __restrict__ out) {
    __shared__ float warp_part[WPB];

    const int wid  = threadIdx.x >> 5;
    const int lane = threadIdx.x & 31;
    const int gw   = blockIdx.x * WPB + wid;       // 0..25087

    const int rowA = gw * 2;
    const int rowB = rowA + 1;

    const int bA = rowA / SM1, tA = rowA - bA * SM1 + 1;   // 1..49
    const int bB = rowB / SM1, tB = rowB - bB * SM1 + 1;

    // 32-bit float4 offsets (max 31.3M < 2^31) — warp-uniform, UR-promotable
    const float4* __restrict__ batch4 = (const float4*)batch;
    const int offA = (bA * SMAX + tA) * ROW4;
    const int offB = (bB * SMAX + tB) * ROW4;

    int jA = -1, jB = -1;
    int c = 0;

    // Phase 1: scan both rows in lockstep. 4 LDG.128 per lane per iter
    // (2 KB/warp in flight), detection granularity 256 floats/row,
    // ONE ballot on the common path. All loads unguarded: i0 <= 607 < 612
    // always; i1 clamped to 611 (dup reads in last chunk are L1 hits, and
    // locate uses the clamped index so j stays exact).
    #pragma unroll 1
    for (; c < VEC4; c += 64) {
        const int i0 = c + lane;                   // max 607
        const int i1 = min(i0 + 32, VEC4 - 1);     // clamp (last chunk only)
        float4 a0 = batch4[offA + i0];
        float4 b0 = batch4[offB + i0];
        float4 a1 = batch4[offA + i1];
        float4 b1 = batch4[offB + i1];

        const unsigned na = nz4(a0) | nz4(a1);
        const unsigned nb = nz4(b0) | nz4(b1);

        if (__ballot_sync(FULLM, na | nb)) {
            const unsigned wa = __ballot_sync(FULLM, na != 0);
            const unsigned wb = __ballot_sync(FULLM, nb != 0);
            if (wa) {
                const int loc = na ? locate_pair(a0, a1, i0, i1) : -1;
                jA = __reduce_max_sync(FULLM, loc);
            }
            if (wb) {
                const int loc = nb ? locate_pair(b0, b1, i0, i1) : -1;
                jB = __reduce_max_sync(FULLM, loc);
            }
            c += 64;
            break;
        }
    }

    // Phase 2: finish whichever stream is still unresolved (at most one
    // in practice), same 2-load/iter shape as R6.
    if (jA < 0) {
        #pragma unroll 1
        for (int cc = c; cc < VEC4; cc += 64) {
            const int i0 = cc + lane;
            const int i1 = min(i0 + 32, VEC4 - 1);
            float4 a0 = batch4[offA + i0];
            float4 a1 = batch4[offA + i1];
            const unsigned na = nz4(a0) | nz4(a1);
            if (__ballot_sync(FULLM, na)) {
                const int loc = na ? locate_pair(a0, a1, i0, i1) : -1;
                jA = __reduce_max_sync(FULLM, loc);
                break;
            }
        }
    }
    if (jB < 0) {
        #pragma unroll 1
        for (int cc = c; cc < VEC4; cc += 64) {
            const int i0 = cc + lane;
            const int i1 = min(i0 + 32, VEC4 - 1);
            float4 b0 = batch4[offB + i0];
            float4 b1 = batch4[offB + i1];
            const unsigned nb = nz4(b0) | nz4(b1);
            if (__ballot_sync(FULLM, nb)) {
                const int loc = nb ? locate_pair(b0, b1, i0, i1) : -1;
                jB = __reduce_max_sync(FULLM, loc);
                break;
            }
        }
    }

    // Per-warp epilogue (lane 0): both pred gathers back-to-back, then logs.
    if (lane == 0) {
        float contrib = 0.0f;
        const int pA_off = (bA * SMAX + (tA - 1)) * NQ;
        const int pB_off = (bB * SMAX + (tB - 1)) * NQ;
        float pA = 0.0f, pB = 0.0f;
        if (jA >= 0)
            pA = __ldg(pred + pA_off + ((jA < NQ) ? jA : (jA - NQ)));
        if (jB >= 0)
            pB = __ldg(pred + pB_off + ((jB < NQ) ? jB : (jB - NQ)));
        if (jA >= 0 && pA > 0.0f)
            contrib -= __logf((jA < NQ) ? pA : (1.0f - pA));
        if (jB >= 0 && pB > 0.0f)
            contrib -= __logf((jB < NQ) ? pB : (1.0f - pB));
        warp_part[wid] = contrib;
    }
    __syncthreads();

    // CTA epilogue: bucketed atomic (3136 CTAs over 64 padded lines =
    // 49 ops/address, invisible), last CTA folds the final reduction
    // (replaces the init kernel -> one launch total).
    if (threadIdx.x == 0) {
        float s = 0.0f;
        #pragma unroll
        for (int w = 0; w < WPB; ++w) s += warp_part[w];
        atomicAdd(&g_partials[(blockIdx.x & (NBUCK - 1)) * BSTRIDE], s);
        __threadfence();
        const unsigned prev = atomicAdd(&g_count, 1u);
        if (prev == BLOCKS - 1) {
            // All other CTAs' partials are visible (fence before their inc).
            float tot = 0.0f;
            #pragma unroll
            for (int i = 0; i < NBUCK; ++i)
                tot += atomicExch(&g_partials[i * BSTRIDE], 0.0f); // read+reset
            out[0] = tot;
            atomicExch(&g_count, 0u);   // reset for next graph replay
        }
    }
}

extern "C" void kernel_launch(void* const* d_in, const int* in_sizes, int n_in,
                              void* d_out, int out_size) {
    const float* pred  = (const float*)d_in[0];
    const float* batch = (const float*)d_in[1];
    float* out = (float*)d_out;

    loss_kernel<<<BLOCKS, THREADS>>>(pred, batch, out);
}

// round 17
// speedup vs baseline: 1.1406x; 1.0573x over previous
#include <cuda_runtime.h>

#define NQ     1224
#define TWOQ   2448
#define SMAX   50
#define SM1    (SMAX - 1)
#define ROWS   (1024 * SM1)            // 50176
#define VEC4   (TWOQ / 4)              // 612 float4 per batch row
#define ROW4   VEC4
#define WPB    8
#define THREADS 256
#define BLOCKS (ROWS / (WPB * 2))      // 3136 (2 rows per warp)
#define FULLM  0xffffffffu

__global__ void init_out_kernel(float* out) {
    if (threadIdx.x == 0) out[0] = 0.0f;
}

__device__ __forceinline__ unsigned nz4(const float4& v) {
    return __float_as_uint(v.x) | __float_as_uint(v.y) |
           __float_as_uint(v.z) | __float_as_uint(v.w);
}

__device__ __forceinline__ int locate4(const float4& v, int i) {
    int base = i * 4;
    if (v.x != 0.0f) return base;
    if (v.y != 0.0f) return base + 1;
    if (v.z != 0.0f) return base + 2;
    return base + 3;
}

// position within the (v0 @ i0, v1 @ i0+32) pair; caller guarantees nonzero
__device__ __forceinline__ int locate_pair(const float4& v0, const float4& v1,
                                           int i0) {
    return nz4(v0) ? locate4(v0, i0) : locate4(v1, i0 + 32);
}

__global__ __launch_bounds__(THREADS, 8)
void loss_kernel(const float* __restrict__ pred,
                 const float* __restrict__ batch,
                 float* __restrict__ out) {
    __shared__ float warp_part[WPB];

    const int wid  = threadIdx.x >> 5;
    const int lane = threadIdx.x & 31;
    const int gw   = blockIdx.x * WPB + wid;       // 0..25087

    const int rowA = gw * 2;
    const int rowB = rowA + 1;

    const int bA = rowA / SM1, tA = rowA - bA * SM1 + 1;   // 1..49
    const int bB = rowB / SM1, tB = rowB - bB * SM1 + 1;

    // 32-bit float4 offsets (max 31.3M < 2^31) — warp-uniform, UR-promotable
    const float4* __restrict__ batch4 = (const float4*)batch;
    const int offA = (bA * SMAX + tA) * ROW4;
    const int offB = (bB * SMAX + tB) * ROW4;

    const float4 z = make_float4(0.f, 0.f, 0.f, 0.f);

    int jA = -1, jB = -1;
    int c = 0;

    // Phase 1: scan both rows in lockstep. 4 LDG.128 per lane per iter
    // (2 KB/warp in flight), detection granularity 256 floats/row,
    // ONE ballot on the common path. __ldcs: pure streaming data, evict-first.
    #pragma unroll 1
    for (; c < VEC4; c += 64) {
        const int i0 = c + lane;            // max 607 < 612
        const int i1 = i0 + 32;             // max 639 -> guard
        const bool g = (i1 < VEC4);
        float4 a0 = __ldcs(batch4 + offA + i0);
        float4 b0 = __ldcs(batch4 + offB + i0);
        float4 a1 = g ? __ldcs(batch4 + offA + i1) : z;
        float4 b1 = g ? __ldcs(batch4 + offB + i1) : z;

        const unsigned na = nz4(a0) | nz4(a1);
        const unsigned nb = nz4(b0) | nz4(b1);

        if (__ballot_sync(FULLM, na | nb)) {
            const unsigned wa = __ballot_sync(FULLM, na != 0);
            const unsigned wb = __ballot_sync(FULLM, nb != 0);
            if (wa) {
                const int loc = na ? locate_pair(a0, a1, i0) : -1;
                jA = __reduce_max_sync(FULLM, loc);
            }
            if (wb) {
                const int loc = nb ? locate_pair(b0, b1, i0) : -1;
                jB = __reduce_max_sync(FULLM, loc);
            }
            c += 64;
            break;
        }
    }

    // Early gather issue: for any stream already resolved, fire its pred
    // gather NOW so the DRAM latency hides under phase-2 scanning.
    const int pA_off = (bA * SMAX + (tA - 1)) * NQ;
    const int pB_off = (bB * SMAX + (tB - 1)) * NQ;
    float pA = 0.0f, pB = 0.0f;
    const bool earlyA = (jA >= 0);
    const bool earlyB = (jB >= 0);
    if (lane == 0) {
        if (earlyA) pA = __ldg(pred + pA_off + ((jA < NQ) ? jA : (jA - NQ)));
        if (earlyB) pB = __ldg(pred + pB_off + ((jB < NQ) ? jB : (jB - NQ)));
    }

    // Phase 2: finish whichever stream is still unresolved.
    if (jA < 0) {
        #pragma unroll 1
        for (int cc = c; cc < VEC4; cc += 64) {
            const int i0 = cc + lane;
            const int i1 = i0 + 32;
            float4 a0 = __ldcs(batch4 + offA + i0);
            float4 a1 = (i1 < VEC4) ? __ldcs(batch4 + offA + i1) : z;
            const unsigned na = nz4(a0) | nz4(a1);
            if (__ballot_sync(FULLM, na)) {
                const int loc = na ? locate_pair(a0, a1, i0) : -1;
                jA = __reduce_max_sync(FULLM, loc);
                break;
            }
        }
    }
    if (jB < 0) {
        #pragma unroll 1
        for (int cc = c; cc < VEC4; cc += 64) {
            const int i0 = cc + lane;
            const int i1 = i0 + 32;
            float4 b0 = __ldcs(batch4 + offB + i0);
            float4 b1 = (i1 < VEC4) ? __ldcs(batch4 + offB + i1) : z;
            const unsigned nb = nz4(b0) | nz4(b1);
            if (__ballot_sync(FULLM, nb)) {
                const int loc = nb ? locate_pair(b0, b1, i0) : -1;
                jB = __reduce_max_sync(FULLM, loc);
                break;
            }
        }
    }

    // Per-warp epilogue (lane 0): gather any late-resolved stream, then logs.
    if (lane == 0) {
        if (!earlyA && jA >= 0)
            pA = __ldg(pred + pA_off + ((jA < NQ) ? jA : (jA - NQ)));
        if (!earlyB && jB >= 0)
            pB = __ldg(pred + pB_off + ((jB < NQ) ? jB : (jB - NQ)));
        float contrib = 0.0f;
        if (jA >= 0 && pA > 0.0f)
            contrib -= __logf((jA < NQ) ? pA : (1.0f - pA));
        if (jB >= 0 && pB > 0.0f)
            contrib -= __logf((jB < NQ) ? pB : (1.0f - pB));
        warp_part[wid] = contrib;
    }
    __syncthreads();

    // One atomic per block (3136 total) — proven invisible.
    if (threadIdx.x == 0) {
        float s = 0.0f;
        #pragma unroll
        for (int w = 0; w < WPB; ++w) s += warp_part[w];
        atomicAdd(out, s);
    }
}

extern "C" void kernel_launch(void* const* d_in, const int* in_sizes, int n_in,
                              void* d_out, int out_size) {
    const float* pred  = (const float*)d_in[0];
    const float* batch = (const float*)d_in[1];
    float* out = (float*)d_out;

    init_out_kernel<<<1, 32>>>(out);
    loss_kernel<<<BLOCKS, THREADS>>>(pred, batch, out);
}